// round 16
// baseline (speedup 1.0000x reference)
#include <cuda_runtime.h>
#include <cuda_bf16.h>
#include <cstdint>

typedef unsigned long long ull;

#define N_B    4
#define H_N    8
#define D_K    64
#define S_LEN  4096
#define L_LEN  4096
#define NH     32
#define ROWSTR 512               // floats between consecutive s/l rows
#define SPLIT  16
#define CHUNK  256               // S_LEN / SPLIT
#define KSTAGE 32                // s-rows per double-buffered stage
#define NSTG   (CHUNK / KSTAGE)  // 8
#define QS     72                // smem row stride in bf16 halves (144B = 9x16B)

// Persistent scratch (device globals; no runtime allocation).
__device__ float g_partKV[SPLIT * NH * D_K * D_K];   // [split][nh][d][v]
__device__ float g_partKs[SPLIT * NH * D_K];         // [split][nh][d]
__device__ __nv_bfloat16 g_KVhi[NH * D_K * D_K];     // [nh][d][v] bf16 high part
__device__ __nv_bfloat16 g_KVlo[NH * D_K * D_K];     // [nh][d][v] bf16 low part
__device__ float g_Ksum[NH * D_K];                   // [nh][d]

__device__ __forceinline__ float elu1(float x) {
    return x > 0.0f ? x + 1.0f : __expf(x);
}
__device__ __forceinline__ uint32_t smem_u32(const void* p) {
    uint32_t a;
    asm("{ .reg .u64 tmp; cvta.to.shared.u64 tmp, %1; cvt.u32.u64 %0, tmp; }"
        : "=r"(a) : "l"(p));
    return a;
}
__device__ __forceinline__ uint32_t pack_bf16x2(__nv_bfloat16 a, __nv_bfloat16 b) {
    __nv_bfloat162 t = __halves2bfloat162(a, b);
    return *reinterpret_cast<uint32_t*>(&t);
}
__device__ __forceinline__ uint4 ldm_x4(uint32_t addr) {
    uint4 r;
    asm volatile("ldmatrix.sync.aligned.m8n8.x4.shared.b16 {%0,%1,%2,%3}, [%4];"
                 : "=r"(r.x), "=r"(r.y), "=r"(r.z), "=r"(r.w) : "r"(addr));
    return r;
}
__device__ __forceinline__ uint4 ldm_x4t(uint32_t addr) {
    uint4 r;
    asm volatile("ldmatrix.sync.aligned.m8n8.x4.trans.shared.b16 {%0,%1,%2,%3}, [%4];"
                 : "=r"(r.x), "=r"(r.y), "=r"(r.z), "=r"(r.w) : "r"(addr));
    return r;
}
__device__ __forceinline__ void mma_bf16(float* c, uint4 a, uint32_t b0, uint32_t b1) {
    asm volatile(
        "mma.sync.aligned.m16n8k16.row.col.f32.bf16.bf16.f32 "
        "{%0,%1,%2,%3}, {%4,%5,%6,%7}, {%8,%9}, {%0,%1,%2,%3};"
        : "+f"(c[0]), "+f"(c[1]), "+f"(c[2]), "+f"(c[3])
        : "r"(a.x), "r"(a.y), "r"(a.z), "r"(a.w), "r"(b0), "r"(b1));
}

// ---------------------------------------------------------------------------
// Kernel 1 (HMMA): partial KV[d][v] += K^T V over an S-chunk, + partial Ksum.
// 256 threads / 8 warps: warp w owns 16 d-rows (group w&3) x 32 v (half w>>2).
// Smaller per-thread state (acc 16, prefetch 16, ks 8) + launch_bounds(256,3)
// -> 24 warps/SM (was 16) for latency hiding.
// ---------------------------------------------------------------------------
__global__ void __launch_bounds__(256, 3) kv_kernel(const float* __restrict__ Kg,
                                                    const float* __restrict__ Vg) {
    __shared__ __align__(16) __nv_bfloat16 sKhi[2][KSTAGE][QS];
    __shared__ __align__(16) __nv_bfloat16 sKlo[2][KSTAGE][QS];
    __shared__ __align__(16) __nv_bfloat16 sVhi[2][KSTAGE][QS];
    __shared__ __align__(16) __nv_bfloat16 sVlo[2][KSTAGE][QS];
    __shared__ __align__(16) float sRed[KSTAGE][64];

    const int split = blockIdx.x;
    const int nh    = blockIdx.y;
    const int n     = nh >> 3;
    const int h     = nh & 7;

    const size_t rowbase = ((size_t)n * S_LEN + (size_t)split * CHUNK) * ROWSTR + h * D_K;
    const float* Kb = Kg + rowbase;
    const float* Vb = Vg + rowbase;

    const int t  = threadIdx.x;
    const int lr = t >> 3;               // loader row 0..31
    const int c0 = (t & 7) * 8;          // loader col base (8 cols per thread)

    const float* kp = Kb + (size_t)lr * ROWSTR + c0;
    const float* vp = Vb + (size_t)lr * ROWSTR + c0;

    float ks[8];
#pragma unroll
    for (int i = 0; i < 8; i++) ks[i] = 0.0f;

    float4 pk[2], pv[2];
#pragma unroll
    for (int i = 0; i < 2; i++) {
        pk[i] = *(const float4*)(kp + 4 * i);
        pv[i] = *(const float4*)(vp + 4 * i);
    }

    auto store_stage = [&](int b) {
        uint32_t khi[4], klo[4], vhi[4], vlo[4];
#pragma unroll
        for (int i = 0; i < 2; i++) {
            const float f0 = elu1(pk[i].x), f1 = elu1(pk[i].y);
            const float f2 = elu1(pk[i].z), f3 = elu1(pk[i].w);
            ks[4 * i] += f0; ks[4 * i + 1] += f1;
            ks[4 * i + 2] += f2; ks[4 * i + 3] += f3;
            const __nv_bfloat16 h0 = __float2bfloat16(f0), h1 = __float2bfloat16(f1);
            const __nv_bfloat16 h2 = __float2bfloat16(f2), h3 = __float2bfloat16(f3);
            khi[2 * i]     = pack_bf16x2(h0, h1);
            khi[2 * i + 1] = pack_bf16x2(h2, h3);
            klo[2 * i]     = pack_bf16x2(__float2bfloat16(f0 - __bfloat162float(h0)),
                                         __float2bfloat16(f1 - __bfloat162float(h1)));
            klo[2 * i + 1] = pack_bf16x2(__float2bfloat16(f2 - __bfloat162float(h2)),
                                         __float2bfloat16(f3 - __bfloat162float(h3)));
            const float g0 = pv[i].x, g1 = pv[i].y, g2 = pv[i].z, g3 = pv[i].w;
            const __nv_bfloat16 e0 = __float2bfloat16(g0), e1 = __float2bfloat16(g1);
            const __nv_bfloat16 e2 = __float2bfloat16(g2), e3 = __float2bfloat16(g3);
            vhi[2 * i]     = pack_bf16x2(e0, e1);
            vhi[2 * i + 1] = pack_bf16x2(e2, e3);
            vlo[2 * i]     = pack_bf16x2(__float2bfloat16(g0 - __bfloat162float(e0)),
                                         __float2bfloat16(g1 - __bfloat162float(e1)));
            vlo[2 * i + 1] = pack_bf16x2(__float2bfloat16(g2 - __bfloat162float(e2)),
                                         __float2bfloat16(g3 - __bfloat162float(e3)));
        }
        // One conflict-free STS.128 per array (16B-groups (9*lr + c) mod 8 distinct).
        *(uint4*)&sKhi[b][lr][c0] = make_uint4(khi[0], khi[1], khi[2], khi[3]);
        *(uint4*)&sKlo[b][lr][c0] = make_uint4(klo[0], klo[1], klo[2], klo[3]);
        *(uint4*)&sVhi[b][lr][c0] = make_uint4(vhi[0], vhi[1], vhi[2], vhi[3]);
        *(uint4*)&sVlo[b][lr][c0] = make_uint4(vlo[0], vlo[1], vlo[2], vlo[3]);
    };

    store_stage(0);
    __syncthreads();

    // MMA lane addressing (fragment pattern verified in R12; v-half adds bcol offset).
    const int w    = t >> 5;
    const int lane = t & 31;
    const int dg   = w & 3;              // d group: rows 16dg..16dg+15
    const int vh   = w >> 2;             // v half: cols 32vh..32vh+31
    const int arow = (lane & 7) + ((lane >> 4) & 1) * 8;
    const int acol = 16 * dg + ((lane >> 3) & 1) * 8;
    const int brow = (lane & 7) + ((lane >> 3) & 1) * 8;
    const int bcol = 32 * vh + ((lane >> 4) & 1) * 8;

    const uint32_t aKhi = smem_u32(&sKhi[0][arow][acol]);
    const uint32_t aKlo = smem_u32(&sKlo[0][arow][acol]);
    const uint32_t aVhi = smem_u32(&sVhi[0][brow][bcol]);
    const uint32_t aVlo = smem_u32(&sVlo[0][brow][bcol]);
    const uint32_t bufB = KSTAGE * QS * 2;   // bytes per buffer
    const uint32_t ktB  = 16 * QS * 2;       // bytes per 16-row k-step

    float acc[4][4];
#pragma unroll
    for (int nt = 0; nt < 4; nt++)
#pragma unroll
        for (int i = 0; i < 4; i++) acc[nt][i] = 0.0f;

    for (int st = 0; st < NSTG; st++) {
        const int cur = st & 1;
        if (st < NSTG - 1) {
            const float* kp2 = kp + (size_t)(st + 1) * KSTAGE * ROWSTR;
            const float* vp2 = vp + (size_t)(st + 1) * KSTAGE * ROWSTR;
#pragma unroll
            for (int i = 0; i < 2; i++) {
                pk[i] = *(const float4*)(kp2 + 4 * i);
                pv[i] = *(const float4*)(vp2 + 4 * i);
            }
        }

        const uint32_t bo = cur * bufB;
#pragma unroll
        for (int k = 0; k < 2; k++) {
            const uint4 ahi = ldm_x4t(aKhi + bo + k * ktB);
            const uint4 alo = ldm_x4t(aKlo + bo + k * ktB);
#pragma unroll
            for (int np = 0; np < 2; np++) {
                const uint32_t boff = bo + k * ktB + (uint32_t)(16 * np) * 2;
                const uint4 bhi = ldm_x4t(aVhi + boff);
                const uint4 blo = ldm_x4t(aVlo + boff);
                mma_bf16(acc[2 * np],     ahi, bhi.x, bhi.y);
                mma_bf16(acc[2 * np],     ahi, blo.x, blo.y);
                mma_bf16(acc[2 * np],     alo, bhi.x, bhi.y);
                mma_bf16(acc[2 * np + 1], ahi, bhi.z, bhi.w);
                mma_bf16(acc[2 * np + 1], ahi, blo.z, blo.w);
                mma_bf16(acc[2 * np + 1], alo, bhi.z, bhi.w);
            }
        }

        if (st < NSTG - 1) store_stage(cur ^ 1);
        __syncthreads();
    }

    // Ksum: each thread wrote partial sums for its 8 cols; reduce 32 rows.
#pragma unroll
    for (int i = 0; i < 8; i++) sRed[lr][c0 + i] = ks[i];
    __syncthreads();
    if (t < 64) {
        float s = 0.0f;
#pragma unroll
        for (int r = 0; r < KSTAGE; r++) s += sRed[r][t];
        g_partKs[((size_t)split * NH + nh) * D_K + t] = s;
    }

    // Store partial KV fragments.
    {
        float* dst = g_partKV + ((size_t)split * NH + nh) * (D_K * D_K);
        const int r0 = 16 * dg + (lane >> 2);
        const int r1 = r0 + 8;
        const int cb = 32 * vh + 2 * (lane & 3);
#pragma unroll
        for (int nt = 0; nt < 4; nt++) {
            *(float2*)(dst + r0 * 64 + 8 * nt + cb) = make_float2(acc[nt][0], acc[nt][1]);
            *(float2*)(dst + r1 * 64 + 8 * nt + cb) = make_float2(acc[nt][2], acc[nt][3]);
        }
    }
}

// ---------------------------------------------------------------------------
// Kernel 2: reduce partials -> bf16 hi/lo KV + fp32 Ksum.
// ---------------------------------------------------------------------------
__global__ void __launch_bounds__(256) reduce_kernel() {
    const int nh = blockIdx.x;
    const int i4 = blockIdx.y * 256 + threadIdx.x;   // float4 index 0..1023
    float4 s = make_float4(0.f, 0.f, 0.f, 0.f);
    const float4* base = (const float4*)g_partKV;
#pragma unroll
    for (int p = 0; p < SPLIT; p++) {
        const float4 v = base[((size_t)p * NH + nh) * 1024 + i4];
        s.x += v.x; s.y += v.y; s.z += v.z; s.w += v.w;
    }
    __nv_bfloat16 hx = __float2bfloat16(s.x), hy = __float2bfloat16(s.y);
    __nv_bfloat16 hz = __float2bfloat16(s.z), hw = __float2bfloat16(s.w);
    __nv_bfloat16 lx = __float2bfloat16(s.x - __bfloat162float(hx));
    __nv_bfloat16 ly = __float2bfloat16(s.y - __bfloat162float(hy));
    __nv_bfloat16 lz = __float2bfloat16(s.z - __bfloat162float(hz));
    __nv_bfloat16 lw = __float2bfloat16(s.w - __bfloat162float(hw));
    ((uint2*)(g_KVhi + (size_t)nh * 4096))[i4] =
        make_uint2(pack_bf16x2(hx, hy), pack_bf16x2(hz, hw));
    ((uint2*)(g_KVlo + (size_t)nh * 4096))[i4] =
        make_uint2(pack_bf16x2(lx, ly), pack_bf16x2(lz, lw));

    if (blockIdx.y == 0 && threadIdx.x < 64) {
        float z = 0.0f;
#pragma unroll
        for (int p = 0; p < SPLIT; p++)
            z += g_partKs[((size_t)p * NH + nh) * D_K + threadIdx.x];
        g_Ksum[nh * D_K + threadIdx.x] = z;
    }
}

// ---------------------------------------------------------------------------
// Kernel 3 (HMMA): out[l][v] = (Qf[l].KV[:,v]) * Z[l].
// 256 threads / 8 warps: warp w owns 16 l-rows (group w&3) x 32 v (half w>>2).
// ---------------------------------------------------------------------------
__global__ void __launch_bounds__(256, 3) out_kernel(const float* __restrict__ Qg,
                                                     float* __restrict__ Og) {
    __shared__ __align__(16) __nv_bfloat16 sQhi[64][QS];
    __shared__ __align__(16) __nv_bfloat16 sQlo[64][QS];
    __shared__ __align__(16) __nv_bfloat16 sBhi[64][QS];
    __shared__ __align__(16) __nv_bfloat16 sBlo[64][QS];
    __shared__ __align__(16) float sKs[64];
    __shared__ __align__(16) float sZ[64];

    const int nh = blockIdx.y;
    const int l0 = blockIdx.x * 64;
    const int n  = nh >> 3;
    const int h  = nh & 7;
    const int t  = threadIdx.x;

    if (t < 64) sKs[t] = g_Ksum[nh * D_K + t];

    {
        const uint4* bh = (const uint4*)(g_KVhi + (size_t)nh * 4096);
        const uint4* bl = (const uint4*)(g_KVlo + (size_t)nh * 4096);
#pragma unroll
        for (int i = 0; i < 2; i++) {
            const int idx = i * 256 + t;
            const int row = idx >> 3, cg = idx & 7;
            *(uint4*)&sBhi[row][8 * cg] = bh[idx];
            *(uint4*)&sBlo[row][8 * cg] = bl[idx];
        }
    }
    __syncthreads();

    {
        const int qr = t >> 4;               // 0..15
        const int qc = (t & 15) * 4;
        const float* Qb = Qg + ((size_t)n * L_LEN + l0) * ROWSTR + h * D_K;
        float zp[4];
#pragma unroll
        for (int p = 0; p < 4; p++) zp[p] = 0.0f;
#pragma unroll
        for (int p = 0; p < 4; p++) {
            const int l = p * 16 + qr;
            float4 q = *(const float4*)(Qb + (size_t)l * ROWSTR + qc);
            const float f0 = elu1(q.x), f1 = elu1(q.y), f2 = elu1(q.z), f3 = elu1(q.w);
            zp[p] = f0 * sKs[qc] + f1 * sKs[qc + 1] + f2 * sKs[qc + 2] + f3 * sKs[qc + 3];
            const __nv_bfloat16 h0 = __float2bfloat16(f0), h1 = __float2bfloat16(f1);
            const __nv_bfloat16 h2 = __float2bfloat16(f2), h3 = __float2bfloat16(f3);
            *(uint2*)&sQhi[l][qc] = make_uint2(pack_bf16x2(h0, h1), pack_bf16x2(h2, h3));
            *(uint2*)&sQlo[l][qc] = make_uint2(
                pack_bf16x2(__float2bfloat16(f0 - __bfloat162float(h0)),
                            __float2bfloat16(f1 - __bfloat162float(h1))),
                pack_bf16x2(__float2bfloat16(f2 - __bfloat162float(h2)),
                            __float2bfloat16(f3 - __bfloat162float(h3))));
        }
#pragma unroll
        for (int p = 0; p < 4; p++) {
#pragma unroll
            for (int o = 8; o > 0; o >>= 1)
                zp[p] += __shfl_xor_sync(0xFFFFFFFFu, zp[p], o, 16);
        }
        const int c = t & 15;
        if (c < 4) sZ[c * 16 + qr] = 1.0f / (zp[c] + 1e-6f);
    }
    __syncthreads();

    const int w    = t >> 5;
    const int lane = t & 31;
    const int L    = 16 * (w & 3);       // l group
    const int vh   = w >> 2;             // v half

    const int arow = L + (lane & 7) + ((lane >> 3) & 1) * 8;
    const int acol = ((lane >> 4) & 1) * 8;
    const int brow = (lane & 7) + ((lane >> 3) & 1) * 8;
    const int bcol = 32 * vh + ((lane >> 4) & 1) * 8;

    float acc[4][4];
#pragma unroll
    for (int nt = 0; nt < 4; nt++)
#pragma unroll
        for (int i = 0; i < 4; i++) acc[nt][i] = 0.0f;

    const uint32_t aQhi = smem_u32(&sQhi[arow][acol]);
    const uint32_t aQlo = smem_u32(&sQlo[arow][acol]);
    const uint32_t aBhi = smem_u32(&sBhi[brow][bcol]);
    const uint32_t aBlo = smem_u32(&sBlo[brow][bcol]);

#pragma unroll
    for (int k = 0; k < 4; k++) {
        const uint4 ahi = ldm_x4(aQhi + (uint32_t)(16 * k) * 2);
        const uint4 alo = ldm_x4(aQlo + (uint32_t)(16 * k) * 2);
#pragma unroll
        for (int np = 0; np < 2; np++) {
            const uint32_t boff = ((uint32_t)(16 * k) * QS + (uint32_t)(16 * np)) * 2;
            const uint4 bhi = ldm_x4t(aBhi + boff);
            const uint4 blo = ldm_x4t(aBlo + boff);
            mma_bf16(acc[2 * np],     ahi, bhi.x, bhi.y);
            mma_bf16(acc[2 * np],     ahi, blo.x, blo.y);
            mma_bf16(acc[2 * np],     alo, bhi.x, bhi.y);
            mma_bf16(acc[2 * np + 1], ahi, bhi.z, bhi.w);
            mma_bf16(acc[2 * np + 1], ahi, blo.z, blo.w);
            mma_bf16(acc[2 * np + 1], alo, bhi.z, bhi.w);
        }
    }

    {
        const int r0 = L + (lane >> 2);
        const int r1 = r0 + 8;
        const float z0 = sZ[r0], z1 = sZ[r1];
        float* o0 = Og + ((size_t)(n * L_LEN + l0 + r0)) * ROWSTR + h * D_K + 32 * vh;
        float* o1 = Og + ((size_t)(n * L_LEN + l0 + r1)) * ROWSTR + h * D_K + 32 * vh;
        const int cb = 2 * (lane & 3);
#pragma unroll
        for (int nt = 0; nt < 4; nt++) {
            *(float2*)(o0 + 8 * nt + cb) = make_float2(acc[nt][0] * z0, acc[nt][1] * z0);
            *(float2*)(o1 + 8 * nt + cb) = make_float2(acc[nt][2] * z1, acc[nt][3] * z1);
        }
    }
}

// ---------------------------------------------------------------------------
extern "C" void kernel_launch(void* const* d_in, const int* in_sizes, int n_in,
                              void* d_out, int out_size) {
    (void)in_sizes; (void)n_in; (void)out_size;
    const float* Q = (const float*)d_in[0];
    const float* K = (const float*)d_in[1];
    const float* V = (const float*)d_in[2];
    float* O = (float*)d_out;

    kv_kernel<<<dim3(SPLIT, NH), 256>>>(K, V);
    reduce_kernel<<<dim3(NH, 4), 256>>>();
    out_kernel<<<dim3(L_LEN / 64, NH), 256>>>(Q, O);
}